// round 8
// baseline (speedup 1.0000x reference)
#include <cuda_runtime.h>
#include <cuda_bf16.h>
#include <math.h>

// ElevationSConvResidualEncoder — GB300 sm_103a
//
// Dead-code proof (round 0, confirmed rel_err=2e-7 across all rounds):
//   mem = sigmoid(o)*tanh(syn) <= 1.0 always => spike = (mem-1 > 0) == 0 always
//   => pooled == 0 => residual == proj_b
//   => out[0] = relu(distance @ Wd^T + bd)
//      out[1] = relu(azimuth  @ Wa^T + ba)
//      out[2] = relu(relu(elev @ We^T + be) + 0.4*sigmoid(gain)*proj_b)
//
// Round-8 (= round-7 resubmit after broker timeout; never measured).
// Launch-overhead floor regime (T_ovh + 1 cold DRAM RT + warp tail).
// Half-warp-per-output: lanes 0-15 -> batch b0, lanes 16-31 -> batch b0+1,
// 16 K-elems (4 float4) per lane.
//   - reduction is a 4-step butterfly within each half (no cross-half
//     exchange/select): shortest serial SHFL chain of any shape tried.
//   - W lines requested identically by both halves -> intra-instruction
//     broadcast, no extra memory wavefronts; W still read once from DRAM.
//   - 4 accumulators, tree combine; stores in parallel from lanes 0 and 16.
// Shape: warp per (m, j, batch-pair): 6144 warps, 384 blocks x 512 thr,
// single wave.

#define HID 512
#define KDIM 256
#define N_WARP (3 * HID * 4)
#define THREADS 512

__global__ __launch_bounds__(THREADS) void enc_out_kernel(
    const float* __restrict__ distance,
    const float* __restrict__ azimuth,
    const float* __restrict__ elevation,
    const float* __restrict__ Wd, const float* __restrict__ bd,
    const float* __restrict__ Wa, const float* __restrict__ ba,
    const float* __restrict__ We, const float* __restrict__ be,
    const float* __restrict__ proj_b,
    const float* __restrict__ residual_gain,
    float* __restrict__ out)
{
    const int gwarp = blockIdx.x * (THREADS / 32) + (threadIdx.x >> 5);
    const int lane  = threadIdx.x & 31;
    const int half  = lane >> 4;         // 0 or 1 -> which batch of the pair
    const int l     = lane & 15;         // position within half-warp

    const int m  = gwarp >> 11;          // 0..2
    const int r  = gwarp & 2047;
    const int j  = r >> 2;               // 0..511
    const int b0 = (r & 3) * 2;          // batches b0, b0+1
    const int b  = b0 + half;

    const float* x;
    const float* W;
    const float* bias;
    if (m == 0)      { x = distance;  W = Wd; bias = bd; }
    else if (m == 1) { x = azimuth;   W = Wa; bias = ba; }
    else             { x = elevation; W = We; bias = be; }

    // ---- issue ALL loads up front (single memory-latency exposure) ----
    // Each lane covers K-elems [l*16, l*16+16). Both halves read the same W
    // lines (broadcast within each load instruction).
    const float4* wv = reinterpret_cast<const float4*>(W + (size_t)j * KDIM) + l * 4;
    const float4* xv = reinterpret_cast<const float4*>(x + (size_t)b * KDIM) + l * 4;

    const float4 w0 = wv[0];
    const float4 w1 = wv[1];
    const float4 w2 = wv[2];
    const float4 w3 = wv[3];
    const float4 x0 = xv[0];
    const float4 x1 = xv[1];
    const float4 x2 = xv[2];
    const float4 x3 = xv[3];

    // Scalar tail dependencies, hoisted to overlap the vector-load wait.
    const float bj = __ldg(bias + j);
    float addj = 0.0f;
    if (m == 2) {
        const float g = __ldg(residual_gain);
        addj = (0.4f / (1.0f + __expf(-g))) * __ldg(proj_b + j);
    }

    // ---- 16 FMAs as 4 independent depth-4 chains, tree combine ----
    float s0 = x0.x * w0.x;
    float s1 = x1.x * w1.x;
    float s2 = x2.x * w2.x;
    float s3 = x3.x * w3.x;
    s0 = fmaf(x0.y, w0.y, s0);  s1 = fmaf(x1.y, w1.y, s1);
    s2 = fmaf(x2.y, w2.y, s2);  s3 = fmaf(x3.y, w3.y, s3);
    s0 = fmaf(x0.z, w0.z, s0);  s1 = fmaf(x1.z, w1.z, s1);
    s2 = fmaf(x2.z, w2.z, s2);  s3 = fmaf(x3.z, w3.z, s3);
    s0 = fmaf(x0.w, w0.w, s0);  s1 = fmaf(x1.w, w1.w, s1);
    s2 = fmaf(x2.w, w2.w, s2);  s3 = fmaf(x3.w, w3.w, s3);
    float v = (s0 + s1) + (s2 + s3);

    // ---- 4-step butterfly within each 16-lane half ----
    #pragma unroll
    for (int off = 8; off; off >>= 1)
        v += __shfl_xor_sync(0xffffffffu, v, off);
    // lane 0 holds batch b0's sum; lane 16 holds batch b0+1's sum.

    if (l == 0) {
        float res = fmaxf(v + bj, 0.0f);
        if (m == 2) res = fmaxf(res + addj, 0.0f);
        out[((size_t)m << 12) + (size_t)b * HID + j] = res;
    }
}

extern "C" void kernel_launch(void* const* d_in, const int* in_sizes, int n_in,
                              void* d_out, int out_size)
{
    // 0 distance 1 azimuth 2 elevation 3 receive_spikes 4 spike_count
    // 5 Wd 6 bd 7 Wa 8 ba 9 We 10 be 11 conv_W 12 conv_b 13 proj_W 14 proj_b
    // 15 residual_gain
    (void)in_sizes; (void)n_in; (void)out_size;
    const float* distance  = (const float*)d_in[0];
    const float* azimuth   = (const float*)d_in[1];
    const float* elevation = (const float*)d_in[2];
    const float* Wd        = (const float*)d_in[5];
    const float* bd        = (const float*)d_in[6];
    const float* Wa        = (const float*)d_in[7];
    const float* ba        = (const float*)d_in[8];
    const float* We        = (const float*)d_in[9];
    const float* be        = (const float*)d_in[10];
    const float* proj_b    = (const float*)d_in[14];
    const float* gain      = (const float*)d_in[15];
    float* out = (float*)d_out;

    const int blocks = N_WARP / (THREADS / 32);   // 384
    enc_out_kernel<<<blocks, THREADS>>>(distance, azimuth, elevation,
                                        Wd, bd, Wa, ba, We, be,
                                        proj_b, gain, out);
}

// round 9
// speedup vs baseline: 1.2389x; 1.2389x over previous
#include <cuda_runtime.h>
#include <cuda_bf16.h>
#include <math.h>

// ElevationSConvResidualEncoder — GB300 sm_103a — FINAL (round-6 config,
// best measured: 5.79us kernel / 6.66us wall)
//
// Dead-code proof (round 0, confirmed rel_err~2e-7 across all rounds):
//   mem = sigmoid(o)*tanh(syn) <= 1.0 always => spike = (mem-1 > 0) == 0 always
//   => pooled == 0 => residual == proj_b
//   => out[0] = relu(distance @ Wd^T + bd)
//      out[1] = relu(azimuth  @ Wa^T + ba)
//      out[2] = relu(relu(elev @ We^T + be) + 0.4*sigmoid(gain)*proj_b)
//   The 133 MB receive_spikes tensor and the ConvLSTM scan never affect out.
//
// Regime: launch-overhead floor (~T_ovh + one cold-DRAM round-trip + tail).
// Winning configuration:
//   - warp per (m, j, batch-pair): 6144 warps, 384 blocks x 512 thr, 1 wave
//   - contiguous 32B-lane-stride loads (fully coalesced; round-8 showed the
//     64B-stride half-warp variant costs +2us in L1 wavefronts)
//   - all loads front-issued; scalar tail deps (bias/proj_b/gain) hoisted
//   - tree-shaped FMA (dep depth 5)
//   - folded dual reduction: 1 cross-half exchange + 4-step butterfly
//     (6 SHFLs for both outputs), parallel stores from lanes 0 and 16
//   - W read exactly once from DRAM (1.57 MB)

#define HID 512
#define KDIM 256
#define N_WARP (3 * HID * 4)
#define THREADS 512

__global__ __launch_bounds__(THREADS) void enc_out_kernel(
    const float* __restrict__ distance,
    const float* __restrict__ azimuth,
    const float* __restrict__ elevation,
    const float* __restrict__ Wd, const float* __restrict__ bd,
    const float* __restrict__ Wa, const float* __restrict__ ba,
    const float* __restrict__ We, const float* __restrict__ be,
    const float* __restrict__ proj_b,
    const float* __restrict__ residual_gain,
    float* __restrict__ out)
{
    const int gwarp = blockIdx.x * (THREADS / 32) + (threadIdx.x >> 5);
    const int lane  = threadIdx.x & 31;

    const int m  = gwarp >> 11;          // 0..2
    const int r  = gwarp & 2047;
    const int j  = r >> 2;               // 0..511
    const int b0 = (r & 3) * 2;          // batches b0, b0+1

    const float* x;
    const float* W;
    const float* bias;
    if (m == 0)      { x = distance;  W = Wd; bias = bd; }
    else if (m == 1) { x = azimuth;   W = Wa; bias = ba; }
    else             { x = elevation; W = We; bias = be; }

    // ---- issue ALL loads up front (single memory-latency exposure) ----
    // Lane covers k in [lane*8, lane*8+8): 32B lane stride, fully coalesced.
    const float4* wv  = reinterpret_cast<const float4*>(W + (size_t)j * KDIM) + lane * 2;
    const float4* xva = reinterpret_cast<const float4*>(x + (size_t)b0 * KDIM) + lane * 2;
    const float4* xvb = xva + (KDIM / 4);

    const float4 w0 = wv[0];
    const float4 w1 = wv[1];
    const float4 a0 = xva[0];
    const float4 a1 = xva[1];
    const float4 c0 = xvb[0];
    const float4 c1 = xvb[1];

    // Scalar tail dependencies, hoisted to overlap the vector-load wait.
    const float bj = bias[j];
    float addj = 0.0f;
    if (m == 2) {
        const float g = residual_gain[0];
        addj = (0.4f / (1.0f + __expf(-g))) * proj_b[j];
    }

    // ---- tree-shaped dot products (dep depth 5 instead of 8) ----
    float sa0 = a0.x * w0.x;
    float sa1 = a1.x * w1.x;
    float sb0 = c0.x * w0.x;
    float sb1 = c1.x * w1.x;
    sa0 = fmaf(a0.y, w0.y, sa0);  sa1 = fmaf(a1.y, w1.y, sa1);
    sb0 = fmaf(c0.y, w0.y, sb0);  sb1 = fmaf(c1.y, w1.y, sb1);
    sa0 = fmaf(a0.z, w0.z, sa0);  sa1 = fmaf(a1.z, w1.z, sa1);
    sb0 = fmaf(c0.z, w0.z, sb0);  sb1 = fmaf(c1.z, w1.z, sb1);
    sa0 = fmaf(a0.w, w0.w, sa0);  sa1 = fmaf(a1.w, w1.w, sa1);
    sb0 = fmaf(c0.w, w0.w, sb0);  sb1 = fmaf(c1.w, w1.w, sb1);
    const float sa = sa0 + sa1;
    const float sb = sb0 + sb1;

    // ---- folded dual reduction ----
    // One cross-half exchange routes sa-pairs to lanes 0-15 and sb-pairs to
    // lanes 16-31, then a single 4-step butterfly finishes both halves.
    const float ta = __shfl_xor_sync(0xffffffffu, sa, 16);
    const float tb = __shfl_xor_sync(0xffffffffu, sb, 16);
    float v = (lane < 16) ? (sa + ta) : (sb + tb);
    #pragma unroll
    for (int off = 8; off; off >>= 1)
        v += __shfl_xor_sync(0xffffffffu, v, off);
    // lane 0 holds batch b0's sum; lane 16 holds batch b0+1's sum.

    if ((lane & 15) == 0) {
        float res = fmaxf(v + bj, 0.0f);
        if (m == 2) res = fmaxf(res + addj, 0.0f);
        const int b = b0 + (lane >> 4);
        out[((size_t)m << 12) + (size_t)b * HID + j] = res;
    }
}

extern "C" void kernel_launch(void* const* d_in, const int* in_sizes, int n_in,
                              void* d_out, int out_size)
{
    // 0 distance 1 azimuth 2 elevation 3 receive_spikes 4 spike_count
    // 5 Wd 6 bd 7 Wa 8 ba 9 We 10 be 11 conv_W 12 conv_b 13 proj_W 14 proj_b
    // 15 residual_gain
    (void)in_sizes; (void)n_in; (void)out_size;
    const float* distance  = (const float*)d_in[0];
    const float* azimuth   = (const float*)d_in[1];
    const float* elevation = (const float*)d_in[2];
    const float* Wd        = (const float*)d_in[5];
    const float* bd        = (const float*)d_in[6];
    const float* Wa        = (const float*)d_in[7];
    const float* ba        = (const float*)d_in[8];
    const float* We        = (const float*)d_in[9];
    const float* be        = (const float*)d_in[10];
    const float* proj_b    = (const float*)d_in[14];
    const float* gain      = (const float*)d_in[15];
    float* out = (float*)d_out;

    const int blocks = N_WARP / (THREADS / 32);   // 384
    enc_out_kernel<<<blocks, THREADS>>>(distance, azimuth, elevation,
                                        Wd, bd, Wa, ba, We, be,
                                        proj_b, gain, out);
}

// round 14
// speedup vs baseline: 1.4233x; 1.1488x over previous
#include <cuda_runtime.h>
#include <cuda_bf16.h>
#include <math.h>

// ElevationSConvResidualEncoder — GB300 sm_103a — FINAL
// (round-6 configuration; best measured 5.79us kernel / 6.62us wall;
//  identical-binary band: kernel 5.79-6.08us, wall 6.62-7.90us — noise)
//
// Dead-code proof (round 0, confirmed rel_err~2e-7 across all rounds):
//   mem = sigmoid(o)*tanh(syn) <= 1.0 always => spike = (mem-1 > 0) == 0 always
//   => pooled == 0 => residual == proj_b
//   => out[0] = relu(distance @ Wd^T + bd)
//      out[1] = relu(azimuth  @ Wa^T + ba)
//      out[2] = relu(relu(elev @ We^T + be) + 0.4*sigmoid(gain)*proj_b)
//   The 133 MB receive_spikes tensor and the ConvLSTM scan never affect out.
//
// Regime: launch-overhead floor (~T_ovh + one cold-DRAM round-trip + tail).
// Winning configuration:
//   - warp per (m, j, batch-pair): 6144 warps, 384 blocks x 512 thr, 1 wave
//   - contiguous 32B-lane-stride loads, fully coalesced (round-8 showed the
//     64B-stride variant costs +2us in L1 wavefront replays)
//   - all loads front-issued; scalar tail deps (bias/proj_b/gain) hoisted
//   - tree-shaped FMA (dep depth 5)
//   - folded dual reduction: 1 cross-half exchange + 4-step butterfly
//     (6 SHFLs for both outputs), parallel stores from lanes 0 and 16
//   - W read exactly once from DRAM (1.57 MB)

#define HID 512
#define KDIM 256
#define N_WARP (3 * HID * 4)
#define THREADS 512

__global__ __launch_bounds__(THREADS) void enc_out_kernel(
    const float* __restrict__ distance,
    const float* __restrict__ azimuth,
    const float* __restrict__ elevation,
    const float* __restrict__ Wd, const float* __restrict__ bd,
    const float* __restrict__ Wa, const float* __restrict__ ba,
    const float* __restrict__ We, const float* __restrict__ be,
    const float* __restrict__ proj_b,
    const float* __restrict__ residual_gain,
    float* __restrict__ out)
{
    const int gwarp = blockIdx.x * (THREADS / 32) + (threadIdx.x >> 5);
    const int lane  = threadIdx.x & 31;

    const int m  = gwarp >> 11;          // 0..2
    const int r  = gwarp & 2047;
    const int j  = r >> 2;               // 0..511
    const int b0 = (r & 3) * 2;          // batches b0, b0+1

    const float* x;
    const float* W;
    const float* bias;
    if (m == 0)      { x = distance;  W = Wd; bias = bd; }
    else if (m == 1) { x = azimuth;   W = Wa; bias = ba; }
    else             { x = elevation; W = We; bias = be; }

    // ---- issue ALL loads up front (single memory-latency exposure) ----
    // Lane covers k in [lane*8, lane*8+8): 32B lane stride, fully coalesced.
    const float4* wv  = reinterpret_cast<const float4*>(W + (size_t)j * KDIM) + lane * 2;
    const float4* xva = reinterpret_cast<const float4*>(x + (size_t)b0 * KDIM) + lane * 2;
    const float4* xvb = xva + (KDIM / 4);

    const float4 w0 = wv[0];
    const float4 w1 = wv[1];
    const float4 a0 = xva[0];
    const float4 a1 = xva[1];
    const float4 c0 = xvb[0];
    const float4 c1 = xvb[1];

    // Scalar tail dependencies, hoisted to overlap the vector-load wait.
    const float bj = bias[j];
    float addj = 0.0f;
    if (m == 2) {
        const float g = residual_gain[0];
        addj = (0.4f / (1.0f + __expf(-g))) * proj_b[j];
    }

    // ---- tree-shaped dot products (dep depth 5 instead of 8) ----
    float sa0 = a0.x * w0.x;
    float sa1 = a1.x * w1.x;
    float sb0 = c0.x * w0.x;
    float sb1 = c1.x * w1.x;
    sa0 = fmaf(a0.y, w0.y, sa0);  sa1 = fmaf(a1.y, w1.y, sa1);
    sb0 = fmaf(c0.y, w0.y, sb0);  sb1 = fmaf(c1.y, w1.y, sb1);
    sa0 = fmaf(a0.z, w0.z, sa0);  sa1 = fmaf(a1.z, w1.z, sa1);
    sb0 = fmaf(c0.z, w0.z, sb0);  sb1 = fmaf(c1.z, w1.z, sb1);
    sa0 = fmaf(a0.w, w0.w, sa0);  sa1 = fmaf(a1.w, w1.w, sa1);
    sb0 = fmaf(c0.w, w0.w, sb0);  sb1 = fmaf(c1.w, w1.w, sb1);
    const float sa = sa0 + sa1;
    const float sb = sb0 + sb1;

    // ---- folded dual reduction ----
    // One cross-half exchange routes sa-pairs to lanes 0-15 and sb-pairs to
    // lanes 16-31, then a single 4-step butterfly finishes both halves.
    const float ta = __shfl_xor_sync(0xffffffffu, sa, 16);
    const float tb = __shfl_xor_sync(0xffffffffu, sb, 16);
    float v = (lane < 16) ? (sa + ta) : (sb + tb);
    #pragma unroll
    for (int off = 8; off; off >>= 1)
        v += __shfl_xor_sync(0xffffffffu, v, off);
    // lane 0 holds batch b0's sum; lane 16 holds batch b0+1's sum.

    if ((lane & 15) == 0) {
        float res = fmaxf(v + bj, 0.0f);
        if (m == 2) res = fmaxf(res + addj, 0.0f);
        const int b = b0 + (lane >> 4);
        out[((size_t)m << 12) + (size_t)b * HID + j] = res;
    }
}

extern "C" void kernel_launch(void* const* d_in, const int* in_sizes, int n_in,
                              void* d_out, int out_size)
{
    // 0 distance 1 azimuth 2 elevation 3 receive_spikes 4 spike_count
    // 5 Wd 6 bd 7 Wa 8 ba 9 We 10 be 11 conv_W 12 conv_b 13 proj_W 14 proj_b
    // 15 residual_gain
    (void)in_sizes; (void)n_in; (void)out_size;
    const float* distance  = (const float*)d_in[0];
    const float* azimuth   = (const float*)d_in[1];
    const float* elevation = (const float*)d_in[2];
    const float* Wd        = (const float*)d_in[5];
    const float* bd        = (const float*)d_in[6];
    const float* Wa        = (const float*)d_in[7];
    const float* ba        = (const float*)d_in[8];
    const float* We        = (const float*)d_in[9];
    const float* be        = (const float*)d_in[10];
    const float* proj_b    = (const float*)d_in[14];
    const float* gain      = (const float*)d_in[15];
    float* out = (float*)d_out;

    const int blocks = N_WARP / (THREADS / 32);   // 384
    enc_out_kernel<<<blocks, THREADS>>>(distance, azimuth, elevation,
                                        Wd, bd, Wa, ba, We, be,
                                        proj_b, gain, out);
}

// round 15
// speedup vs baseline: 1.4299x; 1.0047x over previous
#include <cuda_runtime.h>
#include <cuda_bf16.h>
#include <math.h>

// ElevationSConvResidualEncoder — GB300 sm_103a — FINAL (locked)
// Round-6 configuration; three clean identical-binary samples:
//   kernel {5.79, 6.08, 6.08} us, wall {6.62, 6.88, 7.90} us, rel_err 2.19e-7.
//
// Dead-code proof (round 0, confirmed every passing round):
//   mem = sigmoid(o)*tanh(syn) <= 1.0 always => spike = (mem-1 > 0) == 0 always
//   => pooled == 0 => residual == proj_b
//   => out[0] = relu(distance @ Wd^T + bd)
//      out[1] = relu(azimuth  @ Wa^T + ba)
//      out[2] = relu(relu(elev @ We^T + be) + 0.4*sigmoid(gain)*proj_b)
//   The 133 MB receive_spikes tensor and the ConvLSTM scan never affect out.
//
// Regime: launch-overhead floor (~T_ovh + one cold-DRAM round-trip + tail).
// Winning configuration:
//   - warp per (m, j, batch-pair): 6144 warps, 384 blocks x 512 thr, 1 wave
//   - contiguous 32B-lane-stride loads, fully coalesced (round-8 showed the
//     64B-stride variant costs +2us in L1 wavefront replays)
//   - all loads front-issued; scalar tail deps (bias/proj_b/gain) hoisted
//   - tree-shaped FMA (dep depth 5)
//   - folded dual reduction: 1 cross-half exchange + 4-step butterfly
//     (6 SHFLs for both outputs), parallel stores from lanes 0 and 16
//   - W read exactly once from DRAM (1.57 MB)

#define HID 512
#define KDIM 256
#define N_WARP (3 * HID * 4)
#define THREADS 512

__global__ __launch_bounds__(THREADS) void enc_out_kernel(
    const float* __restrict__ distance,
    const float* __restrict__ azimuth,
    const float* __restrict__ elevation,
    const float* __restrict__ Wd, const float* __restrict__ bd,
    const float* __restrict__ Wa, const float* __restrict__ ba,
    const float* __restrict__ We, const float* __restrict__ be,
    const float* __restrict__ proj_b,
    const float* __restrict__ residual_gain,
    float* __restrict__ out)
{
    const int gwarp = blockIdx.x * (THREADS / 32) + (threadIdx.x >> 5);
    const int lane  = threadIdx.x & 31;

    const int m  = gwarp >> 11;          // 0..2
    const int r  = gwarp & 2047;
    const int j  = r >> 2;               // 0..511
    const int b0 = (r & 3) * 2;          // batches b0, b0+1

    const float* x;
    const float* W;
    const float* bias;
    if (m == 0)      { x = distance;  W = Wd; bias = bd; }
    else if (m == 1) { x = azimuth;   W = Wa; bias = ba; }
    else             { x = elevation; W = We; bias = be; }

    // ---- issue ALL loads up front (single memory-latency exposure) ----
    // Lane covers k in [lane*8, lane*8+8): 32B lane stride, fully coalesced.
    const float4* wv  = reinterpret_cast<const float4*>(W + (size_t)j * KDIM) + lane * 2;
    const float4* xva = reinterpret_cast<const float4*>(x + (size_t)b0 * KDIM) + lane * 2;
    const float4* xvb = xva + (KDIM / 4);

    const float4 w0 = wv[0];
    const float4 w1 = wv[1];
    const float4 a0 = xva[0];
    const float4 a1 = xva[1];
    const float4 c0 = xvb[0];
    const float4 c1 = xvb[1];

    // Scalar tail dependencies, hoisted to overlap the vector-load wait.
    const float bj = bias[j];
    float addj = 0.0f;
    if (m == 2) {
        const float g = residual_gain[0];
        addj = (0.4f / (1.0f + __expf(-g))) * proj_b[j];
    }

    // ---- tree-shaped dot products (dep depth 5 instead of 8) ----
    float sa0 = a0.x * w0.x;
    float sa1 = a1.x * w1.x;
    float sb0 = c0.x * w0.x;
    float sb1 = c1.x * w1.x;
    sa0 = fmaf(a0.y, w0.y, sa0);  sa1 = fmaf(a1.y, w1.y, sa1);
    sb0 = fmaf(c0.y, w0.y, sb0);  sb1 = fmaf(c1.y, w1.y, sb1);
    sa0 = fmaf(a0.z, w0.z, sa0);  sa1 = fmaf(a1.z, w1.z, sa1);
    sb0 = fmaf(c0.z, w0.z, sb0);  sb1 = fmaf(c1.z, w1.z, sb1);
    sa0 = fmaf(a0.w, w0.w, sa0);  sa1 = fmaf(a1.w, w1.w, sa1);
    sb0 = fmaf(c0.w, w0.w, sb0);  sb1 = fmaf(c1.w, w1.w, sb1);
    const float sa = sa0 + sa1;
    const float sb = sb0 + sb1;

    // ---- folded dual reduction ----
    // One cross-half exchange routes sa-pairs to lanes 0-15 and sb-pairs to
    // lanes 16-31, then a single 4-step butterfly finishes both halves.
    const float ta = __shfl_xor_sync(0xffffffffu, sa, 16);
    const float tb = __shfl_xor_sync(0xffffffffu, sb, 16);
    float v = (lane < 16) ? (sa + ta) : (sb + tb);
    #pragma unroll
    for (int off = 8; off; off >>= 1)
        v += __shfl_xor_sync(0xffffffffu, v, off);
    // lane 0 holds batch b0's sum; lane 16 holds batch b0+1's sum.

    if ((lane & 15) == 0) {
        float res = fmaxf(v + bj, 0.0f);
        if (m == 2) res = fmaxf(res + addj, 0.0f);
        const int b = b0 + (lane >> 4);
        out[((size_t)m << 12) + (size_t)b * HID + j] = res;
    }
}

extern "C" void kernel_launch(void* const* d_in, const int* in_sizes, int n_in,
                              void* d_out, int out_size)
{
    // 0 distance 1 azimuth 2 elevation 3 receive_spikes 4 spike_count
    // 5 Wd 6 bd 7 Wa 8 ba 9 We 10 be 11 conv_W 12 conv_b 13 proj_W 14 proj_b
    // 15 residual_gain
    (void)in_sizes; (void)n_in; (void)out_size;
    const float* distance  = (const float*)d_in[0];
    const float* azimuth   = (const float*)d_in[1];
    const float* elevation = (const float*)d_in[2];
    const float* Wd        = (const float*)d_in[5];
    const float* bd        = (const float*)d_in[6];
    const float* Wa        = (const float*)d_in[7];
    const float* ba        = (const float*)d_in[8];
    const float* We        = (const float*)d_in[9];
    const float* be        = (const float*)d_in[10];
    const float* proj_b    = (const float*)d_in[14];
    const float* gain      = (const float*)d_in[15];
    float* out = (float*)d_out;

    const int blocks = N_WARP / (THREADS / 32);   // 384
    enc_out_kernel<<<blocks, THREADS>>>(distance, azimuth, elevation,
                                        Wd, bd, Wa, ba, We, be,
                                        proj_b, gain, out);
}